// round 7
// baseline (speedup 1.0000x reference)
#include <cuda_runtime.h>
#include <cuda_fp16.h>
#include <cuda_bf16.h>
#include <cstdint>

#define NJ 17
#define DM 128
#define NEDGE 49
#define NROWS 66096          // 3888 * 17
#define NFR 3888
#define MTILES 517           // ceil(66096/128)
#define NCHUNK 10            // 640 / 64
#define KSTRIDE 136          // smem row stride (bf16 elems), conflict-free ldmatrix

// ---------------- device scratch ----------------
__device__ float g_X0[(size_t)NROWS * DM];
__device__ float g_skip[NROWS];
__device__ __align__(16) __nv_bfloat16 g_ah[(size_t)MTILES * 128 * 128];
__device__ __align__(16) __nv_bfloat16 g_al[(size_t)MTILES * 128 * 128];
__device__ __align__(16) __nv_bfloat16 g_bh[640 * 128];
__device__ __align__(16) __nv_bfloat16 g_bl[640 * 128];
__device__ float g_bias[640];
__device__ __align__(16) __half g_lr[(size_t)NROWS * 512];
__device__ __align__(16) float g_v[(size_t)NROWS * DM];

// ---------------- adjacency ----------------
__device__ __constant__ int c_row_start[18] =
    {0,4,7,10,12,15,18,20,23,28,31,33,36,39,41,44,47,49};
__device__ __constant__ signed char c_nbr[NEDGE] = {
    0,1,4,7,  0,1,2,  1,2,3,  2,3,  0,4,5,  4,5,6,  5,6,  0,7,8,
    7,8,9,11,14,  8,9,10,  9,10,  8,11,12,  11,12,13,  12,13,
    8,14,15,  14,15,16,  15,16};
__device__ __constant__ signed char c_erow[NEDGE] = {
    0,0,0,0,  1,1,1,  2,2,2,  3,3,  4,4,4,  5,5,5,  6,6,  7,7,7,
    8,8,8,8,8,  9,9,9,  10,10,  11,11,11,  12,12,12,  13,13,
    14,14,14,  15,15,15,  16,16};

// ---------------- helpers ----------------
__device__ __forceinline__ uint32_t smem_u32(const void* p) {
    uint32_t a;
    asm("{ .reg .u64 t; cvta.to.shared.u64 t, %1; cvt.u32.u64 %0, t; }" : "=r"(a) : "l"(p));
    return a;
}
__device__ __forceinline__ float warp_sum(float v) {
#pragma unroll
    for (int o = 16; o; o >>= 1) v += __shfl_xor_sync(0xffffffffu, v, o);
    return v;
}
__device__ __forceinline__ void ldm4(uint32_t* r, uint32_t addr) {
    asm volatile("ldmatrix.sync.aligned.m8n8.x4.shared.b16 {%0,%1,%2,%3}, [%4];"
                 : "=r"(r[0]), "=r"(r[1]), "=r"(r[2]), "=r"(r[3]) : "r"(addr));
}
__device__ __forceinline__ void mma_bf16(float* c, const uint32_t* a, const uint32_t* b) {
    asm volatile("mma.sync.aligned.m16n8k16.row.col.f32.bf16.bf16.f32 "
                 "{%0,%1,%2,%3}, {%4,%5,%6,%7}, {%8,%9}, {%0,%1,%2,%3};"
                 : "+f"(c[0]), "+f"(c[1]), "+f"(c[2]), "+f"(c[3])
                 : "r"(a[0]), "r"(a[1]), "r"(a[2]), "r"(a[3]), "r"(b[0]), "r"(b[1]));
}

// LN + skip + bf16 hi/lo split for one row held by one warp (regs n0..n3 at lane*4)
__device__ __forceinline__ void ln_split_row(
    float v0, float v1, float v2, float v3, int lane, size_t grow,
    const float* __restrict__ lg, const float* __restrict__ lb,
    const float* __restrict__ aw, const float* __restrict__ ab)
{
    float m = warp_sum(v0 + v1 + v2 + v3) * (1.0f / 128.0f);
    float dx = v0 - m, dy = v1 - m, dz = v2 - m, dw = v3 - m;
    float ss = warp_sum(dx * dx + dy * dy + dz * dz + dw * dw);
    float rstd = rsqrtf(ss * (1.0f / 128.0f) + 1e-5f);
    int k = lane * 4;
    float n0 = dx * rstd * __ldg(lg + k)     + __ldg(lb + k);
    float n1 = dy * rstd * __ldg(lg + k + 1) + __ldg(lb + k + 1);
    float n2 = dz * rstd * __ldg(lg + k + 2) + __ldg(lb + k + 2);
    float n3 = dw * rstd * __ldg(lg + k + 3) + __ldg(lb + k + 3);
    float ad = warp_sum(n0 * __ldg(aw + k)     + n1 * __ldg(aw + k + 1)
                      + n2 * __ldg(aw + k + 2) + n3 * __ldg(aw + k + 3));
    if (lane == 0) g_skip[grow] = 1.0f / (1.0f + __expf(-(ad + __ldg(ab))));

    __nv_bfloat16 h0 = __float2bfloat16(n0), h1 = __float2bfloat16(n1);
    __nv_bfloat16 h2 = __float2bfloat16(n2), h3 = __float2bfloat16(n3);
    __nv_bfloat162 ph01 = __halves2bfloat162(h0, h1);
    __nv_bfloat162 ph23 = __halves2bfloat162(h2, h3);
    __nv_bfloat162 pl01 = __halves2bfloat162(
        __float2bfloat16(n0 - __bfloat162float(h0)),
        __float2bfloat16(n1 - __bfloat162float(h1)));
    __nv_bfloat162 pl23 = __halves2bfloat162(
        __float2bfloat16(n2 - __bfloat162float(h2)),
        __float2bfloat16(n3 - __bfloat162float(h3)));
    uint2 uh, ul;
    uh.x = *reinterpret_cast<uint32_t*>(&ph01);
    uh.y = *reinterpret_cast<uint32_t*>(&ph23);
    ul.x = *reinterpret_cast<uint32_t*>(&pl01);
    ul.y = *reinterpret_cast<uint32_t*>(&pl23);
    *reinterpret_cast<uint2*>(g_ah + grow * 128 + k) = uh;
    *reinterpret_cast<uint2*>(g_al + grow * 128 + k) = ul;
}

// ---------------- prologue: split weights into bf16 hi/lo, row-major [640][128] ----------------
__global__ void prep_kernel(const float* __restrict__ w1, const float* __restrict__ b1,
                            const float* __restrict__ w2, const float* __restrict__ b2,
                            const float* __restrict__ vw, const float* __restrict__ vb)
{
    int idx = blockIdx.x * blockDim.x + threadIdx.x;
    if (idx < 640 * 128) {
        int n = idx >> 7;
        int k = idx & 127;
        float w = (n < 256) ? w1[k * 256 + n]
                : (n < 512) ? w2[k * 256 + (n - 256)]
                            : vw[k * 128 + (n - 512)];
        __nv_bfloat16 h = __float2bfloat16(w);
        __nv_bfloat16 l = __float2bfloat16(w - __bfloat162float(h));
        g_bh[idx] = h;
        g_bl[idx] = l;
    }
    if (idx < 640) {
        g_bias[idx] = (idx < 256) ? b1[idx]
                    : (idx < 512) ? b2[idx - 256]
                                  : vb[idx - 512];
    }
}

// ---------------- outer LN + first inner LN/split: x -> g_X0, g_ah/al, g_skip ----------------
__global__ __launch_bounds__(256) void outer_fused_kernel(
    const float* __restrict__ x,
    const float* __restrict__ og, const float* __restrict__ ob,
    const float* __restrict__ lg, const float* __restrict__ lb,
    const float* __restrict__ aw, const float* __restrict__ ab)
{
    size_t row = (size_t)blockIdx.x * 8 + (threadIdx.x >> 5);
    int lane = threadIdx.x & 31;
    float4 v = *reinterpret_cast<const float4*>(x + row * DM + lane * 4);
    float m = warp_sum(v.x + v.y + v.z + v.w) * (1.0f / 128.0f);
    float dx = v.x - m, dy = v.y - m, dz = v.z - m, dw = v.w - m;
    float ss = warp_sum(dx * dx + dy * dy + dz * dz + dw * dw);
    float rstd = rsqrtf(ss * (1.0f / 128.0f) + 1e-5f);
    int k = lane * 4;
    float4 o;
    o.x = dx * rstd * __ldg(og + k)     + __ldg(ob + k);
    o.y = dy * rstd * __ldg(og + k + 1) + __ldg(ob + k + 1);
    o.z = dz * rstd * __ldg(og + k + 2) + __ldg(ob + k + 2);
    o.w = dw * rstd * __ldg(og + k + 3) + __ldg(ob + k + 3);
    *reinterpret_cast<float4*>(g_X0 + row * DM + k) = o;
    ln_split_row(o.x, o.y, o.z, o.w, lane, row, lg, lb, aw, ab);
}

// ---------------- GEMM: 128M x 64N tile, K=128 one-shot, 3-term bf16 split ----------------
#define TILE_A (128 * KSTRIDE)
#define TILE_B (64 * KSTRIDE)
#define GEMM_SMEM ((2 * TILE_A + 2 * TILE_B) * 2)   // 104448 bytes -> 2 CTAs/SM

__global__ __launch_bounds__(256) void gemm_kernel()
{
    extern __shared__ __nv_bfloat16 sm[];
    __nv_bfloat16* sAh = sm;
    __nv_bfloat16* sAl = sm + TILE_A;
    __nv_bfloat16* sBh = sm + 2 * TILE_A;
    __nv_bfloat16* sBl = sm + 2 * TILE_A + TILE_B;

    const int tid = threadIdx.x;
    const int mtile = blockIdx.x;
    const int chunk = blockIdx.y;          // 64 output cols per chunk

    {
        const uint4* gAh = reinterpret_cast<const uint4*>(g_ah + (size_t)mtile * 128 * 128);
        const uint4* gAl = reinterpret_cast<const uint4*>(g_al + (size_t)mtile * 128 * 128);
        for (int i = tid; i < 2048; i += 256) {
            int row = i >> 4, c = i & 15;
            int d = row * KSTRIDE + c * 8;
            *reinterpret_cast<uint4*>(sAh + d) = gAh[i];
            *reinterpret_cast<uint4*>(sAl + d) = gAl[i];
        }
        const uint4* gBh = reinterpret_cast<const uint4*>(g_bh + (size_t)chunk * 64 * 128);
        const uint4* gBl = reinterpret_cast<const uint4*>(g_bl + (size_t)chunk * 64 * 128);
        for (int i = tid; i < 1024; i += 256) {
            int row = i >> 4, c = i & 15;
            int d = row * KSTRIDE + c * 8;
            *reinterpret_cast<uint4*>(sBh + d) = gBh[i];
            *reinterpret_cast<uint4*>(sBl + d) = gBl[i];
        }
    }
    __syncthreads();

    const int wid = tid >> 5, lane = tid & 31;
    const int wm = wid >> 1, wn = wid & 1;   // warp tile: 32M x 32N
    const int mBase = wm * 32, nBase = wn * 32;
    const int g = lane >> 3, r = lane & 7;

    const int a_row = r + (g & 1) * 8, a_k = (g >> 1) * 8;
    const int b_n = r + (g >> 1) * 8, b_k = (g & 1) * 8;
    uint32_t aBaseH = smem_u32(sAh) + ((mBase + a_row) * KSTRIDE + a_k) * 2;
    uint32_t aBaseL = smem_u32(sAl) + ((mBase + a_row) * KSTRIDE + a_k) * 2;
    uint32_t bBaseH = smem_u32(sBh) + ((nBase + b_n) * KSTRIDE + b_k) * 2;
    uint32_t bBaseL = smem_u32(sBl) + ((nBase + b_n) * KSTRIDE + b_k) * 2;

    float acc[2][4][4];
#pragma unroll
    for (int mt = 0; mt < 2; mt++)
#pragma unroll
        for (int nt = 0; nt < 4; nt++)
#pragma unroll
            for (int q = 0; q < 4; q++) acc[mt][nt][q] = 0.f;

#pragma unroll 2
    for (int k0 = 0; k0 < 128; k0 += 16) {
        uint32_t ah[2][4], al[2][4], bh[4][2], bl[4][2];
#pragma unroll
        for (int mt = 0; mt < 2; mt++) {
            uint32_t off = (uint32_t)(mt * 16 * KSTRIDE + k0) * 2;
            ldm4(ah[mt], aBaseH + off);
            ldm4(al[mt], aBaseL + off);
        }
#pragma unroll
        for (int p = 0; p < 2; p++) {
            uint32_t off = (uint32_t)(p * 16 * KSTRIDE + k0) * 2;
            uint32_t t[4];
            ldm4(t, bBaseH + off);
            bh[2 * p][0] = t[0]; bh[2 * p][1] = t[1];
            bh[2 * p + 1][0] = t[2]; bh[2 * p + 1][1] = t[3];
            ldm4(t, bBaseL + off);
            bl[2 * p][0] = t[0]; bl[2 * p][1] = t[1];
            bl[2 * p + 1][0] = t[2]; bl[2 * p + 1][1] = t[3];
        }
#pragma unroll
        for (int mt = 0; mt < 2; mt++)
#pragma unroll
            for (int nt = 0; nt < 4; nt++) {
                mma_bf16(acc[mt][nt], ah[mt], bh[nt]);
                mma_bf16(acc[mt][nt], al[mt], bh[nt]);
                mma_bf16(acc[mt][nt], ah[mt], bl[nt]);
            }
    }

    // ---- epilogue: +bias; l,r -> fp16 g_lr; v -> fp32 g_v ----
    const int qrow = lane >> 2, qcol = (lane & 3) * 2;
#pragma unroll
    for (int mt = 0; mt < 2; mt++) {
#pragma unroll
        for (int nt = 0; nt < 4; nt++) {
            int row0 = mtile * 128 + mBase + mt * 16 + qrow;
            int col = nBase + nt * 8 + qcol;          // 0..63 within chunk
            int gcol = chunk * 64 + col;
            float b0 = g_bias[gcol], b1 = g_bias[gcol + 1];
            float c0 = acc[mt][nt][0] + b0, c1 = acc[mt][nt][1] + b1;
            float c2 = acc[mt][nt][2] + b0, c3 = acc[mt][nt][3] + b1;
            if (chunk < 8) {
                if (row0 < NROWS)
                    *reinterpret_cast<__half2*>(&g_lr[(size_t)row0 * 512 + gcol]) =
                        __halves2half2(__float2half(c0), __float2half(c1));
                if (row0 + 8 < NROWS)
                    *reinterpret_cast<__half2*>(&g_lr[(size_t)(row0 + 8) * 512 + gcol]) =
                        __halves2half2(__float2half(c2), __float2half(c3));
            } else {
                int vc = gcol - 512;
                if (row0 < NROWS) {
                    float2 o; o.x = c0; o.y = c1;
                    *reinterpret_cast<float2*>(&g_v[(size_t)row0 * DM + vc]) = o;
                }
                if (row0 + 8 < NROWS) {
                    float2 o; o.x = c2; o.y = c3;
                    *reinterpret_cast<float2*>(&g_v[(size_t)(row0 + 8) * DM + vc]) = o;
                }
            }
        }
    }
}

// ---------------- attention + fused next-iter LN/split ----------------
__global__ __launch_bounds__(128) void attn_fused_kernel(
    const float* __restrict__ psw,
    const float* __restrict__ lg, const float* __restrict__ lb,
    const float* __restrict__ aw, const float* __restrict__ ab,
    float* __restrict__ out, int last)
{
    __shared__ __align__(16) __half LR[NJ * 512];
    __shared__ __align__(16) float V[NJ * DM];
    __shared__ __align__(16) float XNEW[NJ * DM];
    __shared__ float SC[2 * NEDGE];
    __shared__ float SK[NJ];
    __shared__ float PSW[DM];

    const int tid = threadIdx.x;
    const int wid = tid >> 5;
    const int lane = tid & 31;
    const size_t r0 = (size_t)blockIdx.x * NJ;

    {
        const uint4* src = reinterpret_cast<const uint4*>(g_lr + r0 * 512);
        uint4* d = reinterpret_cast<uint4*>(LR);
        for (int i = tid; i < NJ * 512 * 2 / 16; i += 128) d[i] = src[i];
        const uint4* sv = reinterpret_cast<const uint4*>(g_v + r0 * DM);
        uint4* dv = reinterpret_cast<uint4*>(V);
        for (int i = tid; i < NJ * DM * 4 / 16; i += 128) dv[i] = sv[i];
    }
    if (tid < NJ) SK[tid] = g_skip[r0 + tid];
    if (tid < DM) PSW[tid] = psw[tid];
    __syncthreads();

    // scores (49 adjacent pairs x 2 heads)
    for (int t = wid; t < 2 * NEDGE; t += 4) {
        int h = (t >= NEDGE);
        int e = t - h * NEDGE;
        int i = c_erow[e];
        int j = c_nbr[e];
        const __half* lp = LR + i * 512 + h * 128;
        const __half* rp = LR + j * 512 + 256 + h * 128;
        float acc = 0.f;
#pragma unroll
        for (int q = 0; q < 4; q++) {
            int d = lane + 32 * q;
            float u = __half2float(lp[d]) + __half2float(rp[d]);
            acc = fmaf(fmaxf(u, 0.2f * u), PSW[d], acc);
        }
        acc = warp_sum(acc);
        if (lane == 0) SC[t] = acc;
    }
    __syncthreads();

    if (tid < 34) {
        int h = (tid >= NJ);
        int i = tid - h * NJ;
        int rs = c_row_start[i], re = c_row_start[i + 1];
        float m = -1e30f;
        for (int e = rs; e < re; e++) m = fmaxf(m, SC[h * NEDGE + e]);
        float s = 0.f;
        for (int e = rs; e < re; e++) s += __expf(SC[h * NEDGE + e] - m);
        float inv = 1.0f / s;
        for (int e = rs; e < re; e++)
            SC[h * NEDGE + e] = __expf(SC[h * NEDGE + e] - m) * inv;
    }
    __syncthreads();

    // aggregate + gelu + mix; thread tid owns column tid of every row
    const int h = tid >> 6, d = tid & 63;
#pragma unroll 1
    for (int j = 0; j < NJ; j++) {
        int rs = c_row_start[j], re = c_row_start[j + 1];
        float acc = 0.f;
        for (int e = rs; e < re; e++)
            acc = fmaf(SC[h * NEDGE + e], V[(int)c_nbr[e] * DM + h * 64 + d], acc);
        float gl = 0.5f * acc * (1.0f + erff(acc * 0.70710678118654752f));
        float sk = SK[j];
        float val = (1.0f - sk) * gl + sk * g_X0[(r0 + j) * DM + tid];
        if (last) out[(r0 + j) * DM + tid] = val;
        else      XNEW[j * DM + tid] = val;
    }
    if (last) return;
    __syncthreads();

    // fused inner LN + skip + bf16 split for next iteration (warp per row)
    for (int rr = wid; rr < NJ; rr += 4) {
        float4 v = *reinterpret_cast<const float4*>(&XNEW[rr * DM + lane * 4]);
        ln_split_row(v.x, v.y, v.z, v.w, lane, r0 + rr, lg, lb, aw, ab);
    }
}

// ---------------- launch ----------------
extern "C" void kernel_launch(void* const* d_in, const int* in_sizes, int n_in,
                              void* d_out, int out_size) {
    const float* x   = (const float*)d_in[0];
    const float* og  = (const float*)d_in[1];
    const float* ob  = (const float*)d_in[2];
    const float* lg  = (const float*)d_in[3];
    const float* lb  = (const float*)d_in[4];
    const float* aw  = (const float*)d_in[5];
    const float* ab  = (const float*)d_in[6];
    const float* w1  = (const float*)d_in[7];
    const float* b1  = (const float*)d_in[8];
    const float* w2  = (const float*)d_in[9];
    const float* b2  = (const float*)d_in[10];
    const float* psw = (const float*)d_in[11];
    const float* vw  = (const float*)d_in[13];
    const float* vb  = (const float*)d_in[14];
    float* out = (float*)d_out;

    cudaFuncSetAttribute(gemm_kernel,
                         cudaFuncAttributeMaxDynamicSharedMemorySize, GEMM_SMEM);

    prep_kernel<<<(640 * 128 + 255) / 256, 256>>>(w1, b1, w2, b2, vw, vb);
    outer_fused_kernel<<<NROWS / 8, 256>>>(x, og, ob, lg, lb, aw, ab);

    for (int it = 0; it < 4; it++) {
        gemm_kernel<<<dim3(MTILES, NCHUNK), 256, GEMM_SMEM>>>();
        attn_fused_kernel<<<NFR, 128>>>(psw, lg, lb, aw, ab, out, it == 3);
    }
}